// round 13
// baseline (speedup 1.0000x reference)
#include <cuda_runtime.h>

typedef unsigned long long u64;

#define DEVI __device__ __forceinline__

// ---------- packed f32x2 primitives ----------
DEVI u64 pack2(float lo, float hi) {
    u64 d; asm("mov.b64 %0, {%1,%2};" : "=l"(d) : "f"(lo), "f"(hi)); return d;
}
DEVI void unpack2(u64 v, float& lo, float& hi) {
    asm("mov.b64 {%0,%1}, %2;" : "=f"(lo), "=f"(hi) : "l"(v));
}
DEVI u64 fma2(u64 a, u64 b, u64 c) {
    u64 d; asm("fma.rn.f32x2 %0,%1,%2,%3;" : "=l"(d) : "l"(a), "l"(b), "l"(c)); return d;
}
DEVI u64 mul2(u64 a, u64 b) {
    u64 d; asm("mul.rn.f32x2 %0,%1,%2;" : "=l"(d) : "l"(a), "l"(b)); return d;
}
DEVI u64 add2(u64 a, u64 b) {
    u64 d; asm("add.rn.f32x2 %0,%1,%2;" : "=l"(d) : "l"(a), "l"(b)); return d;
}

// ---------- scalar MUFU approx ----------
DEVI float ex2a(float x) { float y; asm("ex2.approx.f32 %0,%1;" : "=f"(y) : "f"(x)); return y; }
DEVI float lg2a(float x) { float y; asm("lg2.approx.f32 %0,%1;" : "=f"(y) : "f"(x)); return y; }
DEVI float rcpa(float x) { float y; asm("rcp.approx.f32 %0,%1;" : "=f"(y) : "f"(x)); return y; }
DEVI float rsqa(float x) { float y; asm("rsqrt.approx.f32 %0,%1;" : "=f"(y) : "f"(x)); return y; }
DEVI float sqta(float x) { float y; asm("sqrt.approx.f32 %0,%1;" : "=f"(y) : "f"(x)); return y; }

// packed helpers around scalar MUFU (pack/unpack are register-pair MOVs)
DEVI u64 rsq2(u64 v) { float a, b; unpack2(v, a, b); return pack2(rsqa(a), rsqa(b)); }
DEVI u64 sqt2(u64 v) { float a, b; unpack2(v, a, b); return pack2(sqta(a), sqta(b)); }

// Input v is PRE-SCALED by 2*log2(e) (folded into the feeding layer's W,b).
// tanh(x) = 1 - 2/(2^(2*log2e*x) + 1). 2 packed fma-pipe ops + 4 MUFU. Err ~1e-6.
#define C_2LOG2E 2.8853900817779268f
DEVI u64 tanh2_pre(u64 v, u64 kONE, u64 kNEG2) {
    float a, b; unpack2(v, a, b);
    u64 e  = pack2(ex2a(a), ex2a(b));
    u64 ap = add2(e, kONE);
    float ea, eb; unpack2(ap, ea, eb);
    u64 r = pack2(rcpa(ea), rcpa(eb));
    return fma2(kNEG2, r, kONE);
}

// sin(theta/2) for theta = atan2(s, c), c^2+s^2 = 1. Branch-free operand
// selection; u = 0.5*(1+|c|) covers both arms without cancellation.
// cos(theta/2) is NOT needed anywhere (sin(1.5*theta) via triple-angle).
DEVI float half_sin(float c, float s) {
    float u   = fmaf(0.5f, fabsf(c), 0.5f);   // 0.5*(1+|c|)
    float ru  = rsqa(u);
    float big = u * ru;                        // sqrt(u) = |sin| when c<0
    float sml = 0.5f * s * ru;                 // signed sin(theta/2) when c>=0
    return (c >= 0.0f) ? sml : copysignf(big, s);
}

// ---------- shared layout (u64 elements, weights duplicated (w,w)) ----------
// All row strides EVEN and all bases 16B-aligned so weight pairs load as LDS.128.
#define OFF_W1   0     // 2x30, stride 30   (scaled by K)
#define OFF_B1   60    // 30                (scaled by K)
#define OFF_W2   96    // 30x30, stride 32  (scaled by K)
#define OFF_B2   1056  // 30                (scaled by K)
#define OFF_W3   1088  // 30x30, stride 32  (scaled by K)
#define OFF_B3   2048  // 30                (scaled by K)
#define OFF_W4   2080  // 30x8, stride 8    (unscaled)
#define OFF_B4   2320  // 8                 (unscaled)
#define OFF_P1   2328  // 2x15, stride 16   (scaled by K)
#define OFF_PB1  2360  // 15                (scaled by K)
#define OFF_P2   2376  // 15x15, stride 16  (scaled by K)
#define OFF_PB2  2616  // 15                (scaled by K)
#define OFF_P3   2632  // 15x15, stride 16  (scaled by K)
#define OFF_PB3  2872  // 15                (scaled by K)
#define OFF_P4   2888  // 15x4, stride 4    (unscaled)
#define OFF_PB4  2948  // 4                 (unscaled)
#define SP_TOT   2952

DEVI void load_dup(u64* dst, const float* src, int n, float scale, int t, int nt) {
    for (int i = t; i < n; i += nt) { float w = src[i] * scale; dst[i] = pack2(w, w); }
}
DEVI void load_pad(u64* dst, const float* src, int n, int cols, int stride, float scale,
                   int t, int nt) {
    for (int i = t; i < n; i += nt) {
        int r = i / cols, c = i - r * cols;
        float w = src[i] * scale;
        dst[r * stride + c] = pack2(w, w);
    }
}

// One dense layer on packed pairs: hout[j] = act(sum_i hin[i]*W[i,j] + B[j])
// Weights read as 16B ulonglong2 pairs -> LDS.128 (STRIDE even, base aligned).
// When ACT, W/B are pre-scaled by 2*log2(e) so tanh2_pre needs no input mul.
template <int IN, int OUT, int STRIDE, bool ACT>
DEVI void layer(const u64* W, const u64* B, const u64* hin, u64* hout,
                u64 kONE, u64 kNEG2) {
    u64 acc[OUT];
#pragma unroll
    for (int j = 0; j + 1 < OUT; j += 2) {
        ulonglong2 bp = *reinterpret_cast<const ulonglong2*>(B + j);
        acc[j] = bp.x; acc[j + 1] = bp.y;
    }
    if (OUT & 1) acc[OUT - 1] = B[OUT - 1];
#pragma unroll
    for (int i = 0; i < IN; i++) {
        u64 hi = hin[i];
        const u64* Wr = W + i * STRIDE;
#pragma unroll
        for (int j = 0; j + 1 < OUT; j += 2) {
            ulonglong2 wp = *reinterpret_cast<const ulonglong2*>(Wr + j);
            acc[j]     = fma2(hi, wp.x, acc[j]);
            acc[j + 1] = fma2(hi, wp.y, acc[j + 1]);
        }
        if (OUT & 1) acc[OUT - 1] = fma2(hi, Wr[OUT - 1], acc[OUT - 1]);
    }
#pragma unroll
    for (int j = 0; j < OUT; j++)
        hout[j] = ACT ? tanh2_pre(acc[j], kONE, kNEG2) : acc[j];
}

__global__ void __launch_bounds__(256) mlp_interior_kernel(
    const float* __restrict__ x, const float* __restrict__ imv, const float* __restrict__ lmbd,
    const float* __restrict__ Ww1, const float* __restrict__ bw1,
    const float* __restrict__ Ww2, const float* __restrict__ bw2,
    const float* __restrict__ Ww3, const float* __restrict__ bw3,
    const float* __restrict__ Ww4, const float* __restrict__ bw4,
    const float* __restrict__ Wp1, const float* __restrict__ bp1,
    const float* __restrict__ Wp2, const float* __restrict__ bp2,
    const float* __restrict__ Wp3, const float* __restrict__ bp3,
    const float* __restrict__ Wp4, const float* __restrict__ bp4,
    float* __restrict__ out, int n)
{
    __shared__ __align__(16) u64 sp[SP_TOT];
    const int t = threadIdx.x, nt = blockDim.x;

    // ---- hoisted per-thread global loads: overlap DRAM latency with weight
    // staging + barrier below (these LDGs are independent of shared memory). ----
    const int gid = blockIdx.x * nt + t;
    const int i0  = gid * 2;             // first of the two points this thread owns
    const bool live = (i0 < n);
    const bool full = (i0 + 1 < n);
    float4 xv = make_float4(0.f, 0.f, 0.f, 0.f);
    if (full) {
        xv = reinterpret_cast<const float4*>(x)[gid];
    } else if (live) {
        xv.x = x[2 * i0]; xv.y = x[2 * i0 + 1]; xv.z = xv.x; xv.w = xv.y;
    }
    const float imx = imv[0], imy = imv[1], lm = lmbd[0];

    const float K = C_2LOG2E;
    load_dup(sp + OFF_W1,  Ww1, 60, K, t, nt);
    load_dup(sp + OFF_B1,  bw1, 30, K, t, nt);
    load_pad(sp + OFF_W2,  Ww2, 900, 30, 32, K, t, nt);
    load_dup(sp + OFF_B2,  bw2, 30, K, t, nt);
    load_pad(sp + OFF_W3,  Ww3, 900, 30, 32, K, t, nt);
    load_dup(sp + OFF_B3,  bw3, 30, K, t, nt);
    load_dup(sp + OFF_W4,  Ww4, 240, 1.0f, t, nt);
    load_dup(sp + OFF_B4,  bw4, 8, 1.0f, t, nt);
    load_pad(sp + OFF_P1,  Wp1, 30, 15, 16, K, t, nt);
    load_dup(sp + OFF_PB1, bp1, 15, K, t, nt);
    load_pad(sp + OFF_P2,  Wp2, 225, 15, 16, K, t, nt);
    load_dup(sp + OFF_PB2, bp2, 15, K, t, nt);
    load_pad(sp + OFF_P3,  Wp3, 225, 15, 16, K, t, nt);
    load_dup(sp + OFF_PB3, bp3, 15, K, t, nt);
    load_dup(sp + OFF_P4,  Wp4, 60, 1.0f, t, nt);
    load_dup(sp + OFF_PB4, bp4, 4, 1.0f, t, nt);
    __syncthreads();

    if (!live) return;

    const bool lm_half = (lm == 0.5f);   // uniform fast path: r^0.5 = sqrt(r)
    const u64 kONE  = pack2(1.0f, 1.0f);
    const u64 kNEG2 = pack2(-2.0f, -2.0f);
    const u64 kTWO  = pack2(2.0f, 2.0f);
    const u64 kN6   = pack2(-6.0f, -6.0f);
    const u64 k15   = pack2(15.0f, 15.0f);
    const u64 kN10  = pack2(-10.0f, -10.0f);
    const u64 k3    = pack2(3.0f, 3.0f);
    const u64 kN4   = pack2(-4.0f, -4.0f);

    // ---- packed geometry ----
    u64 px2 = pack2(xv.x, xv.z), py2 = pack2(xv.y, xv.w);

    // geometry about imv
    u64 dx2 = add2(px2, pack2(-imx, -imx));
    u64 dy2 = add2(py2, pack2(-imy, -imy));
    u64 r22 = fma2(dx2, dx2, mul2(dy2, dy2));
    u64 ir2 = rsq2(r22);
    u64 r_2 = mul2(r22, ir2);                 // r
    u64 cb2 = mul2(dx2, ir2);                 // unit vector x_ba
    u64 sb2 = mul2(dy2, ir2);

    // yita smoothstep argument: clamp(2.5 r - 1.25, 0, 1)  (clamps scalar FMNMX)
    u64 ttl = fma2(pack2(2.5f, 2.5f), r_2, pack2(-1.25f, -1.25f));
    {
        float a, b; unpack2(ttl, a, b);
        ttl = pack2(fminf(fmaxf(a, 0.0f), 1.0f), fminf(fmaxf(b, 0.0f), 1.0f));
    }
    // yita = ((-6 t + 15) t - 10) t^3 + 1
    u64 t32   = mul2(mul2(ttl, ttl), ttl);
    u64 yita2 = fma2(fma2(fma2(kN6, ttl, k15), ttl, kN10), t32, kONE);

    // vphi(x): r0^k sin(k*theta0), k = 0.5, 1, 1.5; x in [0,1)^2 => px >= 0.
    //   v0 = sqrt(r0) sin(th/2) = py / sqrt(2 (r0 + px))   (cancellation-free)
    //   v1 = r0 sin(th)         = py
    //   v2 = r0^1.5 sin(1.5 th) = v0 (3 r0 - 4 v0^2)       (exact triple-angle)
    u64 r022 = fma2(px2, px2, mul2(py2, py2));
    u64 r02_ = sqt2(r022);                                   // r0
    u64 varg = mul2(kTWO, add2(r02_, px2));                  // 2 (r0 + px)
    u64 v0_2 = mul2(py2, rsq2(varg));                        // v0
    u64 v0sq = mul2(v0_2, v0_2);
    u64 v2_2 = mul2(v0_2, fma2(kN4, v0sq, mul2(k3, r02_)));  // v0 (3 r0 - 4 v0^2)

    // vphi_sig(x_ba): unit vector; c can be negative -> scalar sin-only half-angle
    float cb_[2], sb_[2];
    unpack2(cb2, cb_[0], cb_[1]);
    unpack2(sb2, sb_[0], sb_[1]);
    u64 u0_2 = pack2(half_sin(cb_[0], sb_[0]), half_sin(cb_[1], sb_[1]));
    // u2 = sin(1.5 th) = u0*(3 - 4 u0^2)
    u64 u0sq = mul2(u0_2, u0_2);
    u64 u2_2 = mul2(u0_2, fma2(kN4, u0sq, k3));

    // r^lambda (uniform fast path for lambda = 0.5)
    u64 rl2;
    if (lm_half) {
        rl2 = sqt2(r_2);
    } else {
        float ra, rb; unpack2(r_2, ra, rb);
        rl2 = pack2(ex2a(lm * lg2a(ra)), ex2a(lm * lg2a(rb)));
    }

    // ---- w-MLP (2 -> 30 -> 30 -> 30 -> 8), two points packed per lane ----
    u64 xin[2] = { px2, py2 };
    u64 h[30];
    layer<2, 30, 30, true>(sp + OFF_W1, sp + OFF_B1, xin, h, kONE, kNEG2);
    layer<30, 30, 32, true>(sp + OFF_W2, sp + OFF_B2, h, h, kONE, kNEG2);
    layer<30, 30, 32, true>(sp + OFF_W3, sp + OFF_B3, h, h, kONE, kNEG2);
    u64 wreg[8];
    layer<30, 8, 8, false>(sp + OFF_W4, sp + OFF_B4, h, wreg, kONE, kNEG2);

    // ---- phi-MLP (2 -> 15 -> 15 -> 15 -> 4) on x_ba ----
    u64 bin[2] = { cb2, sb2 };
    u64 g[15];
    layer<2, 15, 16, true>(sp + OFF_P1, sp + OFF_PB1, bin, g, kONE, kNEG2);
    layer<15, 15, 16, true>(sp + OFF_P2, sp + OFF_PB2, g, g, kONE, kNEG2);
    layer<15, 15, 16, true>(sp + OFF_P3, sp + OFF_PB3, g, g, kONE, kNEG2);
    u64 freg[4];
    layer<15, 4, 4, false>(sp + OFF_P4, sp + OFF_PB4, g, freg, kONE, kNEG2);

    // ---- combine (fully packed; wreg/freg already hold per-point lane pairs) ----
    // rp = w0 + yita*w4 + (w5*yita+w1)*v0 + (w6*yita+w2)*v1 + (w7*yita+w3)*v2
    u64 big2 = fma2(fma2(wreg[5], yita2, wreg[1]), v0_2,
               fma2(fma2(wreg[6], yita2, wreg[2]), py2,
               mul2(fma2(wreg[7], yita2, wreg[3]), v2_2)));
    u64 rp2  = add2(fma2(yita2, wreg[4], wreg[0]), big2);
    // s = f0 + f1*u0 + f2*u1 + f3*u2
    u64 s2   = add2(freg[0],
               fma2(freg[1], u0_2,
               fma2(freg[2], sb2, mul2(freg[3], u2_2))));
    // res = rp + s*yita*rl
    u64 res2 = fma2(mul2(s2, yita2), rl2, rp2);

    float r0o, r1o; unpack2(res2, r0o, r1o);
    if (full) {
        reinterpret_cast<float2*>(out)[gid] = make_float2(r0o, r1o);
    } else {
        out[i0] = r0o;
    }
}

extern "C" void kernel_launch(void* const* d_in, const int* in_sizes, int n_in,
                              void* d_out, int out_size) {
    const int npts   = in_sizes[0] / 2;       // x is [N, 2]
    const int npairs = (npts + 1) / 2;        // 2 points per thread
    const int threads = 256;                  // halves per-CTA weight-staging redundancy
    const int blocks  = (npairs + threads - 1) / threads;
    mlp_interior_kernel<<<blocks, threads>>>(
        (const float*)d_in[0],  (const float*)d_in[1],  (const float*)d_in[2],
        (const float*)d_in[3],  (const float*)d_in[4],  (const float*)d_in[5],
        (const float*)d_in[6],  (const float*)d_in[7],  (const float*)d_in[8],
        (const float*)d_in[9],  (const float*)d_in[10], (const float*)d_in[11],
        (const float*)d_in[12], (const float*)d_in[13], (const float*)d_in[14],
        (const float*)d_in[15], (const float*)d_in[16], (const float*)d_in[17],
        (const float*)d_in[18],
        (float*)d_out, npts);
}

// round 17
// speedup vs baseline: 1.6218x; 1.6218x over previous
#include <cuda_runtime.h>

typedef unsigned long long u64;

#define DEVI __device__ __forceinline__

// ---------- packed f32x2 primitives ----------
DEVI u64 pack2(float lo, float hi) {
    u64 d; asm("mov.b64 %0, {%1,%2};" : "=l"(d) : "f"(lo), "f"(hi)); return d;
}
DEVI void unpack2(u64 v, float& lo, float& hi) {
    asm("mov.b64 {%0,%1}, %2;" : "=f"(lo), "=f"(hi) : "l"(v));
}
DEVI u64 fma2(u64 a, u64 b, u64 c) {
    u64 d; asm("fma.rn.f32x2 %0,%1,%2,%3;" : "=l"(d) : "l"(a), "l"(b), "l"(c)); return d;
}
DEVI u64 add2(u64 a, u64 b) {
    u64 d; asm("add.rn.f32x2 %0,%1,%2;" : "=l"(d) : "l"(a), "l"(b)); return d;
}

// ---------- scalar MUFU approx ----------
DEVI float ex2a(float x) { float y; asm("ex2.approx.f32 %0,%1;" : "=f"(y) : "f"(x)); return y; }
DEVI float lg2a(float x) { float y; asm("lg2.approx.f32 %0,%1;" : "=f"(y) : "f"(x)); return y; }
DEVI float rcpa(float x) { float y; asm("rcp.approx.f32 %0,%1;" : "=f"(y) : "f"(x)); return y; }
DEVI float rsqa(float x) { float y; asm("rsqrt.approx.f32 %0,%1;" : "=f"(y) : "f"(x)); return y; }
DEVI float sqta(float x) { float y; asm("sqrt.approx.f32 %0,%1;" : "=f"(y) : "f"(x)); return y; }

// Inputs PRE-SCALED by 2*log2(e) (folded into feeding layer's W,b).
// tanh(x) = 1 - 2/(2^(2*log2e*x) + 1). Err ~1e-6.
#define C_2LOG2E 2.8853900817779268f
DEVI u64 tanh2_pre(u64 v, u64 kONE, u64 kNEG2) {
    float a, b; unpack2(v, a, b);
    u64 e  = pack2(ex2a(a), ex2a(b));
    u64 ap = add2(e, kONE);
    float ea, eb; unpack2(ap, ea, eb);
    u64 r = pack2(rcpa(ea), rcpa(eb));
    return fma2(kNEG2, r, kONE);
}
DEVI float tanh1_pre(float a) {           // scalar tail variant
    return fmaf(-2.0f, rcpa(ex2a(a) + 1.0f), 1.0f);
}

// sin(theta/2) for theta = atan2(s, c), c^2+s^2 = 1. Branch-free selects;
// u = 0.5*(1+|c|) covers both arms without cancellation.
DEVI float half_sin(float c, float s) {
    float u   = fmaf(0.5f, fabsf(c), 0.5f);
    float ru  = rsqa(u);
    float big = u * ru;
    float sml = 0.5f * s * ru;
    return (c >= 0.0f) ? sml : copysignf(big, s);
}

// ---------- shared layout: u64 pairs of ADJACENT outputs (no duplication) ----
// pair k of row i = (W[i][2k], W[i][2k+1]); odd-width tail stored in low half.
// All region bases at EVEN u64 index and row strides EVEN -> 16B-aligned rows.
#define OFF_W1   0      // rows=2  cols=30 stride 16
#define OFF_B1   32     // cols=30 (15 pairs)
#define OFF_W2   48     // rows=30 cols=30 stride 16
#define OFF_B2   528
#define OFF_W3   544    // rows=30 cols=30 stride 16
#define OFF_B3   1024
#define OFF_W4   1040   // rows=30 cols=8  stride 4
#define OFF_B4   1160   // 4 pairs
#define OFF_P1   1164   // rows=2  cols=15 stride 8 (7 pairs + tail)
#define OFF_PB1  1180
#define OFF_P2   1188   // rows=15 cols=15 stride 8
#define OFF_PB2  1308
#define OFF_P3   1316
#define OFF_PB3  1436
#define OFF_P4   1444   // rows=15 cols=4  stride 2
#define OFF_PB4  1474   // 2 pairs
#define SP_TOT   1476   // 11.8 KB

// Stage float matrix (rows x cols, row-major) into pair layout with scale.
DEVI void stage_pairs(u64* dst, const float* src, int rows, int cols,
                      int rstride, float scale, int t, int nt) {
    const int np  = cols >> 1;
    const int npe = np + (cols & 1);
    for (int idx = t; idx < rows * npe; idx += nt) {
        int r = idx / npe, k = idx - r * npe;
        if (k < np) {
            dst[r * rstride + k] =
                pack2(src[r * cols + 2 * k] * scale, src[r * cols + 2 * k + 1] * scale);
        } else {
            dst[r * rstride + np] = pack2(src[r * cols + cols - 1] * scale, 0.0f);
        }
    }
}

// Dense layer, OUTPUT-pair packed, one point per thread.
// hout[j] = act(sum_i hin[i]*W[i][j] + B[j]); accumulation completes before
// any hout write, so in-place (hout==hin) is safe.
template <int IN, int OUT, int RSTRIDE, bool ACT>
DEVI void layerO(const u64* W, const u64* B, const float* hin, float* hout,
                 u64 kONE, u64 kNEG2) {
    constexpr int NP   = OUT / 2;
    constexpr bool TL  = (OUT & 1);
    u64 acc[NP];
#pragma unroll
    for (int j = 0; j + 1 < NP; j += 2) {
        ulonglong2 bp = *reinterpret_cast<const ulonglong2*>(B + j);
        acc[j] = bp.x; acc[j + 1] = bp.y;
    }
    if (NP & 1) acc[NP - 1] = B[NP - 1];
    float accT = 0.0f;
    if (TL) { float lo, hi; unpack2(B[NP], lo, hi); accT = lo; }
#pragma unroll
    for (int i = 0; i < IN; i++) {
        float h = hin[i];
        u64 hi2 = pack2(h, h);
        const u64* Wr = W + i * RSTRIDE;
#pragma unroll
        for (int j = 0; j + 1 < NP; j += 2) {
            ulonglong2 wp = *reinterpret_cast<const ulonglong2*>(Wr + j);
            acc[j]     = fma2(hi2, wp.x, acc[j]);
            acc[j + 1] = fma2(hi2, wp.y, acc[j + 1]);
        }
        if (NP & 1) acc[NP - 1] = fma2(hi2, Wr[NP - 1], acc[NP - 1]);
        if (TL) { float lo, hi; unpack2(Wr[NP], lo, hi); accT = fmaf(h, lo, accT); }
    }
#pragma unroll
    for (int j = 0; j < NP; j++) {
        u64 o = ACT ? tanh2_pre(acc[j], kONE, kNEG2) : acc[j];
        unpack2(o, hout[2 * j], hout[2 * j + 1]);
    }
    if (TL) hout[OUT - 1] = ACT ? tanh1_pre(accT) : accT;
}

__global__ void __launch_bounds__(256, 2) mlp_interior_kernel(
    const float* __restrict__ x, const float* __restrict__ imv, const float* __restrict__ lmbd,
    const float* __restrict__ Ww1, const float* __restrict__ bw1,
    const float* __restrict__ Ww2, const float* __restrict__ bw2,
    const float* __restrict__ Ww3, const float* __restrict__ bw3,
    const float* __restrict__ Ww4, const float* __restrict__ bw4,
    const float* __restrict__ Wp1, const float* __restrict__ bp1,
    const float* __restrict__ Wp2, const float* __restrict__ bp2,
    const float* __restrict__ Wp3, const float* __restrict__ bp3,
    const float* __restrict__ Wp4, const float* __restrict__ bp4,
    float* __restrict__ out, int n)
{
    __shared__ __align__(16) u64 sp[SP_TOT];
    const int t = threadIdx.x, nt = blockDim.x;

    // hoisted per-thread input load (overlaps weight staging + barrier)
    const int gid = blockIdx.x * nt + t;
    const bool live = (gid < n);
    float px = 0.f, py = 0.f;
    if (live) {
        float2 xy = reinterpret_cast<const float2*>(x)[gid];
        px = xy.x; py = xy.y;
    }
    const float imx = imv[0], imy = imv[1], lm = lmbd[0];

    const float K = C_2LOG2E;
    stage_pairs(sp + OFF_W1,  Ww1,  2, 30, 16, K,    t, nt);
    stage_pairs(sp + OFF_B1,  bw1,  1, 30, 16, K,    t, nt);
    stage_pairs(sp + OFF_W2,  Ww2, 30, 30, 16, K,    t, nt);
    stage_pairs(sp + OFF_B2,  bw2,  1, 30, 16, K,    t, nt);
    stage_pairs(sp + OFF_W3,  Ww3, 30, 30, 16, K,    t, nt);
    stage_pairs(sp + OFF_B3,  bw3,  1, 30, 16, K,    t, nt);
    stage_pairs(sp + OFF_W4,  Ww4, 30,  8,  4, 1.0f, t, nt);
    stage_pairs(sp + OFF_B4,  bw4,  1,  8,  4, 1.0f, t, nt);
    stage_pairs(sp + OFF_P1,  Wp1,  2, 15,  8, K,    t, nt);
    stage_pairs(sp + OFF_PB1, bp1,  1, 15,  8, K,    t, nt);
    stage_pairs(sp + OFF_P2,  Wp2, 15, 15,  8, K,    t, nt);
    stage_pairs(sp + OFF_PB2, bp2,  1, 15,  8, K,    t, nt);
    stage_pairs(sp + OFF_P3,  Wp3, 15, 15,  8, K,    t, nt);
    stage_pairs(sp + OFF_PB3, bp3,  1, 15,  8, K,    t, nt);
    stage_pairs(sp + OFF_P4,  Wp4, 15,  4,  2, 1.0f, t, nt);
    stage_pairs(sp + OFF_PB4, bp4,  1,  4,  2, 1.0f, t, nt);
    __syncthreads();

    if (!live) return;

    const u64 kONE  = pack2(1.0f, 1.0f);
    const u64 kNEG2 = pack2(-2.0f, -2.0f);

    // ---- scalar geometry (1 point) ----
    float dx = px - imx, dy = py - imy;
    float r2 = fmaf(dx, dx, dy * dy);
    float ir = rsqa(r2);
    float r  = r2 * ir;
    float cb = dx * ir, sb = dy * ir;          // unit vector x_ba

    float tt = fminf(fmaxf(fmaf(2.5f, r, -1.25f), 0.0f), 1.0f);
    float t3 = tt * tt * tt;
    float yita = fmaf(fmaf(fmaf(-6.0f, tt, 15.0f), tt, -10.0f), t3, 1.0f);

    // vphi(x): x in [0,1)^2 => px >= 0
    //   v0 = py / sqrt(2(r0+px));  v1 = py;  v2 = v0*(3 r0 - 4 v0^2)
    float r02 = fmaf(px, px, py * py);
    float r0  = sqta(r02);
    float v0  = py * rsqa(2.0f * (r0 + px));
    float v2  = v0 * fmaf(-4.0f, v0 * v0, 3.0f * r0);

    // vphi_sig(x_ba): unit vector; u2 via triple-angle
    float u0 = half_sin(cb, sb);
    float u2 = u0 * fmaf(-4.0f, u0 * u0, 3.0f);

    // r^lambda (fast path lambda = 0.5)
    float rl = (lm == 0.5f) ? sqta(r) : ex2a(lm * lg2a(r));

    // ---- w-MLP (2 -> 30 -> 30 -> 30 -> 8) ----
    float hb[30];
    {
        float in2[2] = { px, py };
        layerO<2, 30, 16, true>(sp + OFF_W1, sp + OFF_B1, in2, hb, kONE, kNEG2);
    }
    layerO<30, 30, 16, true>(sp + OFF_W2, sp + OFF_B2, hb, hb, kONE, kNEG2);
    layerO<30, 30, 16, true>(sp + OFF_W3, sp + OFF_B3, hb, hb, kONE, kNEG2);
    float wo[8];
    layerO<30, 8, 4, false>(sp + OFF_W4, sp + OFF_B4, hb, wo, kONE, kNEG2);

    // ---- phi-MLP (2 -> 15 -> 15 -> 15 -> 4) on x_ba ----
    float gb[15];
    {
        float bin[2] = { cb, sb };
        layerO<2, 15, 8, true>(sp + OFF_P1, sp + OFF_PB1, bin, gb, kONE, kNEG2);
    }
    layerO<15, 15, 8, true>(sp + OFF_P2, sp + OFF_PB2, gb, gb, kONE, kNEG2);
    layerO<15, 15, 8, true>(sp + OFF_P3, sp + OFF_PB3, gb, gb, kONE, kNEG2);
    float fo[4];
    layerO<15, 4, 2, false>(sp + OFF_P4, sp + OFF_PB4, gb, fo, kONE, kNEG2);

    // ---- combine ----
    float rp = wo[0] + yita * wo[4]
             + fmaf(fmaf(wo[5], yita, wo[1]), v0,
               fmaf(fmaf(wo[6], yita, wo[2]), py,
                    fmaf(wo[7], yita, wo[3]) * v2));
    float s  = fo[0] + fmaf(fo[1], u0, fmaf(fo[2], sb, fo[3] * u2));
    out[gid] = rp + s * yita * rl;
}

extern "C" void kernel_launch(void* const* d_in, const int* in_sizes, int n_in,
                              void* d_out, int out_size) {
    const int npts   = in_sizes[0] / 2;       // x is [N, 2]
    const int threads = 256;
    const int blocks  = (npts + threads - 1) / threads;
    mlp_interior_kernel<<<blocks, threads>>>(
        (const float*)d_in[0],  (const float*)d_in[1],  (const float*)d_in[2],
        (const float*)d_in[3],  (const float*)d_in[4],  (const float*)d_in[5],
        (const float*)d_in[6],  (const float*)d_in[7],  (const float*)d_in[8],
        (const float*)d_in[9],  (const float*)d_in[10], (const float*)d_in[11],
        (const float*)d_in[12], (const float*)d_in[13], (const float*)d_in[14],
        (const float*)d_in[15], (const float*)d_in[16], (const float*)d_in[17],
        (const float*)d_in[18],
        (float*)d_out, npts);
}